// round 13
// baseline (speedup 1.0000x reference)
#include <cuda_runtime.h>

// Problem constants (reference: N=50000, M=8192, C=768, NUM_BATCH=4, GRID=128)
#define NPTS_MAX 50000
#define MTGT_MAX 8192
#define CCH      768
#define NB       4

#define CSHIFT   3                    // cell edge = 8
#define GC       16                   // cells per axis (128 >> 3)
#define NCELLS   (NB * GC * GC * GC)  // 16384
#define CAP      32                   // points per cell (lambda~3)
#define TPBF     1024                 // threads per block (fused kernel)

// ------- device scratch (static; no allocation anywhere) -------
// g_count/g_ovn zero at module load; reset in phase C for the next call.
__device__ int      g_count[NCELLS];
__device__ int2     g_cells[NCELLS * CAP];    // (packed_xyz, orig_idx)
__device__ int      g_ovn;
__device__ int4     g_ovf[NPTS_MAX];          // overflow: (packed, idx, batch, 0)
__device__ unsigned g_best[MTGT_MAX];         // (d2<<16)|idx; rewritten every call

// software grid barrier (gen monotonically increases across replays)
__device__ unsigned          g_barcnt = 0;
__device__ volatile unsigned g_bargen = 0;

__device__ __forceinline__ void gridbar(int nblocks) {
    __syncthreads();
    if (threadIdx.x == 0) {
        unsigned gen = g_bargen;
        __threadfence();                       // publish this block's phase writes
        if (atomicAdd(&g_barcnt, 1u) == (unsigned)nblocks - 1u) {
            g_barcnt = 0;
            __threadfence();
            g_bargen = gen + 1u;               // release all spinners
        } else {
            while (g_bargen == gen) __nanosleep(20);
        }
        __threadfence();
    }
    __syncthreads();
}

// candidate evaluation: packed key = d2*65536 + idx (d2<2^16, idx<2^16)
__device__ __forceinline__ void eval(unsigned tp, int2 q, unsigned& best) {
    unsigned ad = __vabsdiffu4(tp, (unsigned)q.x);    // |dx|,|dy|,|dz|,0 per byte
    best = min(best, __dp4a(ad, ad, 0u) * 65536u + (unsigned)q.y);
}

// single persistent kernel: bin -> bar -> grid-NN search -> bar -> reset+gather
// grid MUST be <= #SMs with <=1024 thr (1 block/SM co-residency guaranteed).
__global__ void __launch_bounds__(TPBF) k_fused(
    const int4* __restrict__ coords, int n,
    const int4* __restrict__ tc, int m,
    const float* __restrict__ feat, float* __restrict__ out)
{
    const int nbk = gridDim.x;
    const int tid = blockIdx.x * TPBF + threadIdx.x;
    const int nth = nbk * TPBF;

    // ---- Phase A: bin source points (g_count zero on entry) ----
    for (int i = tid; i < n; i += nth) {
        int4 r = coords[i];                           // (batch,x,y,z) LDG.128
        int b = r.x & (NB - 1);
        int cell = ((b * GC + (r.w >> CSHIFT)) * GC + (r.z >> CSHIFT)) * GC
                 + (r.y >> CSHIFT);
        int packed = r.y | (r.z << 8) | (r.w << 16);
        int pos = atomicAdd(&g_count[cell], 1);
        if (pos < CAP) g_cells[cell * CAP + pos] = make_int2(packed, i);
        else {                                        // never in practice; airtight
            int op = atomicAdd(&g_ovn, 1);
            g_ovf[op] = make_int4(packed, i, b, 0);
        }
    }
    gridbar(nbk);

    // ---- Phase B: per-target NN search, spread across all SMs ----
    for (int j = blockIdx.x + threadIdx.x * nbk; j < m; j += nth) {
        int4 r = tc[j];
        int b = r.x & (NB - 1);
        unsigned tp = (unsigned)(r.y | (r.z << 8) | (r.w << 16));
        int cx = r.y >> CSHIFT, cy = r.z >> CSHIFT, cz = r.w >> CSHIFT;
        unsigned best = 0xFFFFFFFFu;

        int ovn = g_ovn;                              // normally 0
        for (int o = 0; o < ovn; o++) {
            int4 v = g_ovf[o];
            if (v.z == b) eval(tp, make_int2(v.x, v.y), best);
        }

        // k=1 fast path: 27 cells fully unrolled
        #pragma unroll
        for (int dz = -1; dz <= 1; dz++)
        #pragma unroll
        for (int dy = -1; dy <= 1; dy++)
        #pragma unroll
        for (int dx = -1; dx <= 1; dx++) {
            int x = cx + dx, y = cy + dy, z = cz + dz;
            if ((unsigned)x < GC && (unsigned)y < GC && (unsigned)z < GC) {
                int cell = ((b * GC + z) * GC + y) * GC + x;
                int cnt = min(g_count[cell], CAP);
                const int2* p = &g_cells[cell * CAP];
                for (int q = 0; q < cnt; q++) eval(tp, p[q], best);
            }
        }

        // expand shells only if nearest could lie outside radius 1 (rare).
        // After radius k every unexamined point has d2 >= (8k)^2; stop only on
        // STRICT best_d2 < 64k^2 so equal-d2 outside ties (smaller idx) are
        // still examined -> exact argmin first-index semantics.
        if ((best >> 16) >= 64u) {
            for (int k = 2; k <= GC; k++) {
                int x0 = max(cx - k, 0), x1 = min(cx + k, GC - 1);
                int y0 = max(cy - k, 0), y1 = min(cy + k, GC - 1);
                int z0 = max(cz - k, 0), z1 = min(cz + k, GC - 1);
                for (int z = z0; z <= z1; z++)
                for (int y = y0; y <= y1; y++)
                for (int x = x0; x <= x1; x++) {      // redo-all: min-safe dups
                    int cell = ((b * GC + z) * GC + y) * GC + x;
                    int cnt = min(g_count[cell], CAP);
                    const int2* p = &g_cells[cell * CAP];
                    for (int q = 0; q < cnt; q++) eval(tp, p[q], best);
                }
                if ((best >> 16) < (unsigned)(64 * k * k)) break;
                if (x0 == 0 && x1 == GC - 1 && y0 == 0 && y1 == GC - 1 &&
                    z0 == 0 && z1 == GC - 1) break;
            }
        }
        g_best[j] = best;
    }
    gridbar(nbk);

    // ---- Phase C: reset bin state for next replay + gather rows ----
    for (int i = tid; i < NCELLS; i += nth) g_count[i] = 0;
    if (tid == 0) g_ovn = 0;

    const int chunks = m * (CCH / 16);                // 64B chunks, 48 per row
    for (int cid = tid; cid < chunks; cid += nth) {
        int row = cid / (CCH / 16);
        int sub = cid - row * (CCH / 16);
        unsigned k = g_best[row];
        float4* o = (float4*)(out + (size_t)row * CCH) + sub * 4;
        if (k == 0xFFFFFFFFu) {                       // empty batch -> zeros
            float4 zz = make_float4(0.f, 0.f, 0.f, 0.f);
            o[0] = zz; o[1] = zz; o[2] = zz; o[3] = zz;
        } else {
            const float4* f =
                (const float4*)(feat + (size_t)(k & 0xFFFFu) * CCH) + sub * 4;
            float4 v0 = f[0], v1 = f[1], v2 = f[2], v3 = f[3];
            o[0] = v0; o[1] = v1; o[2] = v2; o[3] = v3;
        }
    }
}

extern "C" void kernel_launch(void* const* d_in, const int* in_sizes, int n_in,
                              void* d_out, int out_size) {
    const float* feat    = (const float*)d_in[0];
    const int4*  coords  = (const int4*)d_in[1];
    const int4*  tcoords = (const int4*)d_in[2];
    float*       out     = (float*)d_out;

    int n = in_sizes[1] / 4;   // 50000
    int m = in_sizes[2] / 4;   // 8192

    int sms = 0;
    cudaDeviceGetAttribute(&sms, cudaDevAttrMultiProcessorCount, 0);
    if (sms < 1) sms = 1;      // 1 block/SM (1024 thr) -> co-resident barrier

    k_fused<<<sms, TPBF>>>(coords, n, tcoords, m, feat, out);
}

// round 14
// speedup vs baseline: 2.1893x; 2.1893x over previous
#include <cuda_runtime.h>

// Problem constants (reference: N=50000, M=8192, C=768, NUM_BATCH=4, GRID=128)
#define NPTS_MAX 50000
#define MTGT_MAX 8192
#define CCH      768
#define NB       4

#define CSHIFT   3                    // cell edge = 8
#define GC       16                   // cells per axis (128 >> 3)
#define NCELLS   (NB * GC * GC * GC)  // 16384
#define CAP      32                   // points per cell (lambda~3)
#define TPBF     1024                 // threads per block (fused kernel)
#define WPB      (TPBF / 32)          // warps per block

// ------- device scratch (static; no allocation anywhere) -------
// g_count/g_ovn zero at module load; reset in phase C for the next call.
__device__ int      g_count[NCELLS];
__device__ int2     g_cells[NCELLS * CAP];    // (packed_xyz, orig_idx)
__device__ int      g_ovn;
__device__ int4     g_ovf[NPTS_MAX];          // overflow: (packed, idx, batch, 0)
__device__ unsigned g_best[MTGT_MAX];         // (d2<<16)|idx; rewritten every call

// software grid barrier (gen monotonically increases across replays)
__device__ unsigned          g_barcnt = 0;
__device__ volatile unsigned g_bargen = 0;

__device__ __forceinline__ void gridbar(int nblocks) {
    __syncthreads();
    if (threadIdx.x == 0) {
        unsigned gen = g_bargen;
        __threadfence();                       // publish this block's phase writes
        if (atomicAdd(&g_barcnt, 1u) == (unsigned)nblocks - 1u) {
            g_barcnt = 0;
            __threadfence();
            g_bargen = gen + 1u;               // release all spinners
        } else {
            while (g_bargen == gen) __nanosleep(20);
        }
        __threadfence();
    }
    __syncthreads();
}

// candidate evaluation: packed key = d2*65536 + idx (d2<2^16, idx<2^16)
__device__ __forceinline__ void eval(unsigned tp, int2 q, unsigned& best) {
    unsigned ad = __vabsdiffu4(tp, (unsigned)q.x);    // |dx|,|dy|,|dz|,0 per byte
    best = min(best, __dp4a(ad, ad, 0u) * 65536u + (unsigned)q.y);
}

// single persistent kernel: bin -> bar -> warp-coop NN search -> bar -> gather
// grid MUST be <= #SMs (1 block/SM co-residency for the software barrier).
__global__ void __launch_bounds__(TPBF) k_fused(
    const int4* __restrict__ coords, int n,
    const int4* __restrict__ tc, int m,
    const float* __restrict__ feat, float* __restrict__ out)
{
    const int nbk  = gridDim.x;
    const int tid  = blockIdx.x * TPBF + threadIdx.x;
    const int nth  = nbk * TPBF;
    const int w    = threadIdx.x >> 5;
    const int lane = threadIdx.x & 31;

    __shared__ int s_pref[WPB][32];
    __shared__ int s_cell[WPB][32];

    // ---- Phase A: bin source points (g_count zero on entry) ----
    for (int i = tid; i < n; i += nth) {
        int4 r = coords[i];                           // (batch,x,y,z) LDG.128
        int b = r.x & (NB - 1);
        int cell = ((b * GC + (r.w >> CSHIFT)) * GC + (r.z >> CSHIFT)) * GC
                 + (r.y >> CSHIFT);
        int packed = r.y | (r.z << 8) | (r.w << 16);
        int pos = atomicAdd(&g_count[cell], 1);
        if (pos < CAP) g_cells[cell * CAP + pos] = make_int2(packed, i);
        else {                                        // never in practice; airtight
            int op = atomicAdd(&g_ovn, 1);
            g_ovf[op] = make_int4(packed, i, b, 0);
        }
    }
    gridbar(nbk);

    // ---- Phase B: warp-cooperative NN search (one warp per target) ----
    const int gwarp  = blockIdx.x * WPB + w;
    const int nwarps = nbk * WPB;
    for (int j = gwarp; j < m; j += nwarps) {
        int4 r = tc[j];                               // broadcast load
        int b = r.x & (NB - 1);
        unsigned tp = (unsigned)(r.y | (r.z << 8) | (r.w << 16));
        int cx = r.y >> CSHIFT, cy = r.z >> CSHIFT, cz = r.w >> CSHIFT;

        // lanes 0..26 own one neighbor cell each -> 27 parallel count loads
        int dx = lane % 3 - 1, dy = (lane / 3) % 3 - 1, dz = lane / 9 - 1;
        int x = cx + dx, y = cy + dy, z = cz + dz;
        bool valid = (lane < 27) && (unsigned)x < GC && (unsigned)y < GC
                                 && (unsigned)z < GC;
        int cell = valid ? ((b * GC + z) * GC + y) * GC + x : 0;
        int cnt  = valid ? min(g_count[cell], CAP) : 0;

        int pref = cnt;                               // warp inclusive scan
        #pragma unroll
        for (int s = 1; s < 32; s <<= 1) {
            int v = __shfl_up_sync(0xFFFFFFFFu, pref, s);
            if (lane >= s) pref += v;
        }
        int S = __shfl_sync(0xFFFFFFFFu, pref, 31);   // total candidates (~82)
        s_pref[w][lane] = pref;                       // nondecreasing, [31]=S
        s_cell[w][lane] = cell;
        __syncwarp();

        unsigned best = 0xFFFFFFFFu;
        for (int t = lane; t < S; t += 32) {          // 32 loads in flight
            int idx = 0;                              // first l with pref[l] > t
            #pragma unroll
            for (int step = 16; step; step >>= 1)
                if (s_pref[w][idx + step - 1] <= t) idx += step;
            int excl = idx ? s_pref[w][idx - 1] : 0;
            int2 q = g_cells[s_cell[w][idx] * CAP + (t - excl)];
            eval(tp, q, best);
        }

        int ovn = g_ovn;                              // normally 0
        for (int o = lane; o < ovn; o += 32) {
            int4 v = g_ovf[o];
            if (v.z == b) eval(tp, make_int2(v.x, v.y), best);
        }

        #pragma unroll
        for (int s = 16; s; s >>= 1)                  // warp min-reduce
            best = min(best, __shfl_xor_sync(0xFFFFFFFFu, best, s));

        // shell expansion: needed only if nearest could lie outside radius 1
        // (p ~ 3e-6). All lanes run identical scalar loop (convergent).
        // After radius k any unexamined point has d2 >= (8k)^2; stop only on
        // STRICT best_d2 < 64k^2 -> exact argmin first-index semantics.
        if ((best >> 16) >= 64u) {
            for (int k = 2; k <= GC; k++) {
                int x0 = max(cx - k, 0), x1 = min(cx + k, GC - 1);
                int y0 = max(cy - k, 0), y1 = min(cy + k, GC - 1);
                int z0 = max(cz - k, 0), z1 = min(cz + k, GC - 1);
                for (int zz = z0; zz <= z1; zz++)
                for (int yy = y0; yy <= y1; yy++)
                for (int xx = x0; xx <= x1; xx++) {   // redo-all: min-safe dups
                    int c2 = ((b * GC + zz) * GC + yy) * GC + xx;
                    int c2n = min(g_count[c2], CAP);
                    const int2* p = &g_cells[c2 * CAP];
                    for (int q = 0; q < c2n; q++) eval(tp, p[q], best);
                }
                if ((best >> 16) < (unsigned)(64 * k * k)) break;
                if (x0 == 0 && x1 == GC - 1 && y0 == 0 && y1 == GC - 1 &&
                    z0 == 0 && z1 == GC - 1) break;
            }
        }
        if (lane == 0) g_best[j] = best;
        __syncwarp();                                 // smem reuse next iter
    }
    gridbar(nbk);

    // ---- Phase C: reset bin state for next replay + gather rows ----
    for (int i = tid; i < NCELLS; i += nth) g_count[i] = 0;
    if (tid == 0) g_ovn = 0;

    const int chunks = m * (CCH / 16);                // 64B chunks, 48 per row
    for (int cid = tid; cid < chunks; cid += nth) {
        int row = cid / (CCH / 16);
        int sub = cid - row * (CCH / 16);
        unsigned k = g_best[row];
        float4* o = (float4*)(out + (size_t)row * CCH) + sub * 4;
        if (k == 0xFFFFFFFFu) {                       // empty batch -> zeros
            float4 zz4 = make_float4(0.f, 0.f, 0.f, 0.f);
            o[0] = zz4; o[1] = zz4; o[2] = zz4; o[3] = zz4;
        } else {
            const float4* f =
                (const float4*)(feat + (size_t)(k & 0xFFFFu) * CCH) + sub * 4;
            float4 v0 = f[0], v1 = f[1], v2 = f[2], v3 = f[3];
            o[0] = v0; o[1] = v1; o[2] = v2; o[3] = v3;
        }
    }
}

extern "C" void kernel_launch(void* const* d_in, const int* in_sizes, int n_in,
                              void* d_out, int out_size) {
    const float* feat    = (const float*)d_in[0];
    const int4*  coords  = (const int4*)d_in[1];
    const int4*  tcoords = (const int4*)d_in[2];
    float*       out     = (float*)d_out;

    int n = in_sizes[1] / 4;   // 50000
    int m = in_sizes[2] / 4;   // 8192

    int sms = 0;
    cudaDeviceGetAttribute(&sms, cudaDevAttrMultiProcessorCount, 0);
    if (sms < 1) sms = 1;      // 1 block/SM (1024 thr) -> co-resident barrier

    k_fused<<<sms, TPBF>>>(coords, n, tcoords, m, feat, out);
}

// round 15
// speedup vs baseline: 3.0415x; 1.3893x over previous
#include <cuda_runtime.h>

// Problem constants (reference: N=50000, M=8192, C=768, NUM_BATCH=4, GRID=128)
#define NPTS_MAX 50000
#define MTGT_MAX 8192
#define CCH      768
#define NB       4

#define CSHIFT   3                    // cell edge = 8
#define GC       16                   // cells per axis (128 >> 3)
#define NCELLS   (NB * GC * GC * GC)  // 16384
#define CAP      32                   // points per cell (lambda~3)
#define TPBF     1024                 // threads per block (fused kernel)
#define WPB      (TPBF / 32)          // warps per block

// ------- device scratch (static; no allocation anywhere) -------
// g_count/g_ovn zero at module load; reset at end of kernel for next call.
__device__ int      g_count[NCELLS];
__device__ int2     g_cells[NCELLS * CAP];    // (packed_xyz, orig_idx)
__device__ int      g_ovn;
__device__ int4     g_ovf[NPTS_MAX];          // overflow: (packed, idx, batch, 0)

// software grid barrier (gen monotonically increases across replays)
__device__ unsigned          g_barcnt = 0;
__device__ volatile unsigned g_bargen = 0;

__device__ __forceinline__ void gridbar(int nblocks) {
    __syncthreads();
    if (threadIdx.x == 0) {
        unsigned gen = g_bargen;
        __threadfence();                       // publish this block's phase writes
        if (atomicAdd(&g_barcnt, 1u) == (unsigned)nblocks - 1u) {
            g_barcnt = 0;
            __threadfence();
            g_bargen = gen + 1u;               // release all spinners
        } else {
            while (g_bargen == gen) __nanosleep(20);
        }
        __threadfence();
    }
    __syncthreads();
}

// candidate evaluation: packed key = d2*65536 + idx (d2<2^16, idx<2^16)
__device__ __forceinline__ void eval(unsigned tp, int2 q, unsigned& best) {
    unsigned ad = __vabsdiffu4(tp, (unsigned)q.x);    // |dx|,|dy|,|dz|,0 per byte
    best = min(best, __dp4a(ad, ad, 0u) * 65536u + (unsigned)q.y);
}

// single persistent kernel:
//   bin -> bar -> warp-coop search + IMMEDIATE row gather -> bar -> reset
// grid MUST be <= #SMs (1 block/SM co-residency for the software barrier).
__global__ void __launch_bounds__(TPBF) k_fused(
    const int4* __restrict__ coords, int n,
    const int4* __restrict__ tc, int m,
    const float* __restrict__ feat, float* __restrict__ out)
{
    const int nbk  = gridDim.x;
    const int tid  = blockIdx.x * TPBF + threadIdx.x;
    const int nth  = nbk * TPBF;
    const int w    = threadIdx.x >> 5;
    const int lane = threadIdx.x & 31;

    __shared__ int s_pref[WPB][32];
    __shared__ int s_cell[WPB][32];

    // ---- Phase A: bin source points (g_count zero on entry) ----
    for (int i = tid; i < n; i += nth) {
        int4 r = coords[i];                           // (batch,x,y,z) LDG.128
        int b = r.x & (NB - 1);
        int cell = ((b * GC + (r.w >> CSHIFT)) * GC + (r.z >> CSHIFT)) * GC
                 + (r.y >> CSHIFT);
        int packed = r.y | (r.z << 8) | (r.w << 16);
        int pos = atomicAdd(&g_count[cell], 1);
        if (pos < CAP) g_cells[cell * CAP + pos] = make_int2(packed, i);
        else {                                        // never in practice; airtight
            int op = atomicAdd(&g_ovn, 1);
            g_ovf[op] = make_int4(packed, i, b, 0);
        }
    }
    gridbar(nbk);

    // ---- Phase B: one warp per target: NN search, then gather the row ----
    const int gwarp  = blockIdx.x * WPB + w;
    const int nwarps = nbk * WPB;
    for (int j = gwarp; j < m; j += nwarps) {
        int4 r = tc[j];                               // broadcast load
        int b = r.x & (NB - 1);
        unsigned tp = (unsigned)(r.y | (r.z << 8) | (r.w << 16));
        int cx = r.y >> CSHIFT, cy = r.z >> CSHIFT, cz = r.w >> CSHIFT;

        // lanes 0..26 own one neighbor cell each -> 27 parallel count loads
        int dx = lane % 3 - 1, dy = (lane / 3) % 3 - 1, dz = lane / 9 - 1;
        int x = cx + dx, y = cy + dy, z = cz + dz;
        bool valid = (lane < 27) && (unsigned)x < GC && (unsigned)y < GC
                                 && (unsigned)z < GC;
        int cell = valid ? ((b * GC + z) * GC + y) * GC + x : 0;
        int cnt  = valid ? min(g_count[cell], CAP) : 0;

        int pref = cnt;                               // warp inclusive scan
        #pragma unroll
        for (int s = 1; s < 32; s <<= 1) {
            int v = __shfl_up_sync(0xFFFFFFFFu, pref, s);
            if (lane >= s) pref += v;
        }
        int S = __shfl_sync(0xFFFFFFFFu, pref, 31);   // total candidates (~82)
        s_pref[w][lane] = pref;                       // nondecreasing, [31]=S
        s_cell[w][lane] = cell;
        __syncwarp();

        unsigned best = 0xFFFFFFFFu;
        for (int t = lane; t < S; t += 32) {          // 32 loads in flight
            int idx = 0;                              // first l with pref[l] > t
            #pragma unroll
            for (int step = 16; step; step >>= 1)
                if (s_pref[w][idx + step - 1] <= t) idx += step;
            int excl = idx ? s_pref[w][idx - 1] : 0;
            int2 q = g_cells[s_cell[w][idx] * CAP + (t - excl)];
            eval(tp, q, best);
        }

        int ovn = g_ovn;                              // normally 0
        for (int o = lane; o < ovn; o += 32) {
            int4 v = g_ovf[o];
            if (v.z == b) eval(tp, make_int2(v.x, v.y), best);
        }

        best = __reduce_min_sync(0xFFFFFFFFu, best);  // REDUX: all lanes get min

        // shell expansion: only if nearest could lie outside radius 1 (p~3e-6).
        // All lanes run identical scalar loop (convergent). After radius k any
        // unexamined point has d2 >= (8k)^2; stop only on STRICT
        // best_d2 < 64k^2 -> exact argmin first-index semantics.
        if ((best >> 16) >= 64u) {
            for (int k = 2; k <= GC; k++) {
                int x0 = max(cx - k, 0), x1 = min(cx + k, GC - 1);
                int y0 = max(cy - k, 0), y1 = min(cy + k, GC - 1);
                int z0 = max(cz - k, 0), z1 = min(cz + k, GC - 1);
                for (int zz = z0; zz <= z1; zz++)
                for (int yy = y0; yy <= y1; yy++)
                for (int xx = x0; xx <= x1; xx++) {   // redo-all: min-safe dups
                    int c2 = ((b * GC + zz) * GC + yy) * GC + xx;
                    int c2n = min(g_count[c2], CAP);
                    const int2* p = &g_cells[c2 * CAP];
                    for (int q = 0; q < c2n; q++) eval(tp, p[q], best);
                }
                if ((best >> 16) < (unsigned)(64 * k * k)) break;
                if (x0 == 0 && x1 == GC - 1 && y0 == 0 && y1 == GC - 1 &&
                    z0 == 0 && z1 == GC - 1) break;
            }
        }

        // ---- gather row j right here (all lanes hold `best`) ----
        float4* o = (float4*)(out + (size_t)j * CCH); // 192 float4 per row
        if (best == 0xFFFFFFFFu) {                    // empty batch -> zeros
            float4 zz4 = make_float4(0.f, 0.f, 0.f, 0.f);
            #pragma unroll
            for (int c = 0; c < CCH / 4 / 32; c++)    // 6 per lane
                o[lane + c * 32] = zz4;
        } else {
            const float4* f =
                (const float4*)(feat + (size_t)(best & 0xFFFFu) * CCH);
            #pragma unroll
            for (int c = 0; c < CCH / 4 / 32; c++)    // 6 LDG.128 in flight
                o[lane + c * 32] = f[lane + c * 32];
        }
        __syncwarp();                                 // smem reuse next iter
    }
    gridbar(nbk);

    // ---- Phase C: reset bin state for the NEXT replay (tiny) ----
    for (int i = tid; i < NCELLS; i += nth) g_count[i] = 0;
    if (tid == 0) g_ovn = 0;
}

extern "C" void kernel_launch(void* const* d_in, const int* in_sizes, int n_in,
                              void* d_out, int out_size) {
    const float* feat    = (const float*)d_in[0];
    const int4*  coords  = (const int4*)d_in[1];
    const int4*  tcoords = (const int4*)d_in[2];
    float*       out     = (float*)d_out;

    int n = in_sizes[1] / 4;   // 50000
    int m = in_sizes[2] / 4;   // 8192

    int sms = 0;
    cudaDeviceGetAttribute(&sms, cudaDevAttrMultiProcessorCount, 0);
    if (sms < 1) sms = 1;      // 1 block/SM (1024 thr) -> co-resident barrier

    k_fused<<<sms, TPBF>>>(coords, n, tcoords, m, feat, out);
}